// round 7
// baseline (speedup 1.0000x reference)
#include <cuda_runtime.h>
#include <cstdint>
#include <cstddef>

// Problem constants
#define NI_   50000
#define B_    64
#define S_    200
#define T_    199      // S-1 recurrent steps
#define H_    256
#define CLS_  8        // CTAs per cluster (share one batch group's h)
#define NB_   4        // batches per cluster

// -------- device-global scratch (no allocation APIs allowed) --------
__device__ float  g_xpre[(size_t)B_ * T_ * 1024];   // masked x_proj + b_lstm, 52 MB
__device__ float  g_states[(size_t)B_ * T_ * H_];   // masked h outputs, 13 MB
__device__ double g_psum[128];
__device__ int    g_pcnt[128];

// -------- packed f32x2 helpers --------
static __device__ __forceinline__ unsigned long long ffma2(unsigned long long a,
                                                           unsigned long long b,
                                                           unsigned long long c) {
    unsigned long long d;
    asm("fma.rn.f32x2 %0, %1, %2, %3;" : "=l"(d) : "l"(a), "l"(b), "l"(c));
    return d;
}
static __device__ __forceinline__ unsigned long long pack2(float x, float y) {
    unsigned long long u;
    asm("mov.b64 %0, {%1, %2};" : "=l"(u) : "f"(x), "f"(y));
    return u;
}
static __device__ __forceinline__ float2 unpack2(unsigned long long u) {
    float2 r;
    asm("mov.b64 {%0, %1}, %2;" : "=f"(r.x), "=f"(r.y) : "l"(u));
    return r;
}
static __device__ __forceinline__ uint32_t smem_u32(const void* p) {
    uint32_t a;
    asm("{ .reg .u64 t; cvta.to.shared.u64 t, %1; cvt.u32.u64 %0, t; }" : "=r"(a) : "l"(p));
    return a;
}
static __device__ __forceinline__ uint32_t ctarank_() {
    uint32_t r; asm("mov.u32 %0, %%cluster_ctarank;" : "=r"(r)); return r;
}
static __device__ __forceinline__ void cluster_sync_() {
    asm volatile("barrier.cluster.arrive.aligned;" ::: "memory");
    asm volatile("barrier.cluster.wait.aligned;" ::: "memory");
}
// store one float into rank p's shared memory at the same offset
static __device__ __forceinline__ void st_cluster_f32(uint32_t local_addr, uint32_t rank, float v) {
    asm volatile(
        "{ .reg .b32 ra; mapa.shared::cluster.u32 ra, %0, %1; "
        "st.shared::cluster.f32 [ra], %2; }"
        :: "r"(local_addr), "r"(rank), "f"(v) : "memory");
}

// ===========================================================================
// Kernel A: x_pre[b][t][j] = mask ? (WihT[it][j] + WihT[NI+ac][j] + b_lstm[j])
//                                 : b_lstm[j]
// (when mask==0 the gates are never used, so bias-only is a safe filler)
// ===========================================================================
__global__ void xpre_kernel(const int* __restrict__ items,
                            const int* __restrict__ actions,
                            const float* __restrict__ WihT,
                            const float* __restrict__ b_lstm) {
    int e4 = blockIdx.x * 256 + threadIdx.x;  // float4 index, total B*T*256
    int j4 = e4 & 255;
    int bt = e4 >> 8;
    int b  = bt / T_;
    int t  = bt - b * T_;
    int it = items[b * S_ + t];
    int ac = actions[b * S_ + t];
    float4 bl = *(const float4*)&b_lstm[j4 * 4];
    float4 o  = bl;
    if (it != 0) {
        float4 w1 = *(const float4*)&WihT[(size_t)it * 1024 + j4 * 4];
        float4 w2 = *(const float4*)&WihT[(size_t)(NI_ + ac) * 1024 + j4 * 4];
        o.x = w1.x + w2.x + bl.x;
        o.y = w1.y + w2.y + bl.y;
        o.z = w1.z + w2.z + bl.z;
        o.w = w1.w + w2.w + bl.w;
    }
    *(float4*)&g_xpre[(size_t)bt * 1024 + j4 * 4] = o;
}

// ===========================================================================
// Kernel B: clustered LSTM recurrence.
// Cluster c -> batches [4c, 4c+4). Rank r owns hidden units [32r, 32r+32),
// i.e. the 128 gate columns { g*256 + 32r + u : g in 0..3, u in 0..31 }.
// Thread t: cg = t&31 -> local cols {4cg..4cg+3}, kg = t>>5 -> K range
// [32kg, 32kg+32). Weight slice (4 cols x 32 K = 128 floats) lives in 64
// f32x2 registers. 8-way split-K partials reduced through SMEM.
// h double-buffered; new h pushed to all 8 ranks via DSMEM; one
// barrier.cluster per step.
// ===========================================================================
__global__ __launch_bounds__(256, 1) __cluster_dims__(CLS_, 1, 1)
void lstm_kernel(const int* __restrict__ items, const float* __restrict__ Whh) {
    __shared__ __align__(16) float h_sh[2][NB_][H_];     // 8 KB
    __shared__ __align__(16) float part[8][NB_][128];    // 16 KB
    __shared__ float gates_sh[NB_][128];                 // 2 KB
    __shared__ float c_sh[NB_][32];                      // 0.5 KB
    __shared__ unsigned char msk[NB_][T_];               // 0.8 KB

    const int tid = threadIdx.x;
    const int r   = (int)ctarank_();
    const int cid = blockIdx.x / CLS_;
    const int bb0 = cid * NB_;

    const int cg    = tid & 31;
    const int kg    = tid >> 5;
    const int kbase = kg * 32;

    // ---- load weight slice into registers (once) ----
    unsigned long long w2r[4][16];
#pragma unroll
    for (int c = 0; c < 4; ++c) {
        int lc = 4 * cg + c;                       // local col 0..127
        int gc = (lc >> 5) * 256 + 32 * r + (lc & 31);  // global gate col
        const float2* wrow = (const float2*)&Whh[(size_t)gc * H_ + kbase];
#pragma unroll
        for (int kk = 0; kk < 16; ++kk) {
            float2 wv = wrow[kk];
            w2r[c][kk] = pack2(wv.x, wv.y);
        }
    }

    // ---- init h, c, masks ----
    for (int i = tid; i < 2 * NB_ * H_; i += 256) ((float*)h_sh)[i] = 0.f;
    for (int i = tid; i < NB_ * 32; i += 256) ((float*)c_sh)[i] = 0.f;
    for (int i = tid; i < NB_ * T_; i += 256) {
        int b = i / T_, tt = i - b * T_;
        msk[b][tt] = (items[(bb0 + b) * S_ + tt] != 0) ? 1 : 0;
    }
    __syncthreads();
    cluster_sync_();   // everyone initialized before any DSMEM pushes

    // finalize mapping: thread handles s0 = tid (b in {0,1}), s1 = tid+256 (b in {2,3})
    const int fb0 = tid >> 7;            // 0..1
    const int fb1 = fb0 + 2;             // 2..3
    const int flc = tid & 127;           // same local col for both
    const int fgc = (flc >> 5) * 256 + 32 * r + (flc & 31);
    const size_t xrow0 = (size_t)(bb0 + fb0) * T_;
    const size_t xrow1 = (size_t)(bb0 + fb1) * T_;

    // update-stage mapping (tid < 128): one (batch, hidden-unit)
    const int ub = tid >> 5;   // 0..3
    const int uu = tid & 31;   // 0..31
    uint32_t haddr[2] = {0, 0};
    if (tid < 128) {
        haddr[0] = smem_u32(&h_sh[0][ub][32 * r + uu]);
        haddr[1] = smem_u32(&h_sh[1][ub][32 * r + uu]);
    }

    for (int t = 0; t < T_; ++t) {
        const int cur = t & 1;
        const int nxt = cur ^ 1;

        // prefetch x_pre for this thread's two finalize slots (latency hidden by FMA loop)
        float xr0 = g_xpre[(xrow0 + t) * 1024 + fgc];
        float xr1 = g_xpre[(xrow1 + t) * 1024 + fgc];

        // ---- FMA loop: 4 cols x 4 batches x 32 K  ->  256 FFMA2 / thread ----
        unsigned long long acc[4][4];
#pragma unroll
        for (int c = 0; c < 4; ++c)
#pragma unroll
            for (int b = 0; b < 4; ++b) acc[c][b] = 0ull;

#pragma unroll
        for (int k4 = 0; k4 < 8; ++k4) {
            ulonglong2 hv[4];
#pragma unroll
            for (int b = 0; b < 4; ++b)
                hv[b] = *(const ulonglong2*)&h_sh[cur][b][kbase + 4 * k4];
#pragma unroll
            for (int b = 0; b < 4; ++b) {
#pragma unroll
                for (int c = 0; c < 4; ++c) {
                    acc[c][b] = ffma2(w2r[c][2 * k4],     hv[b].x, acc[c][b]);
                    acc[c][b] = ffma2(w2r[c][2 * k4 + 1], hv[b].y, acc[c][b]);
                }
            }
        }

        // write split-K partials
#pragma unroll
        for (int c = 0; c < 4; ++c)
#pragma unroll
            for (int b = 0; b < 4; ++b) {
                float2 f = unpack2(acc[c][b]);
                part[kg][b][4 * cg + c] = f.x + f.y;
            }
        __syncthreads();

        // ---- finalize gates: sum 8 partials + x_pre ----
        {
            float g0 = xr0, g1 = xr1;
#pragma unroll
            for (int k = 0; k < 8; ++k) {
                g0 += part[k][fb0][flc];
                g1 += part[k][fb1][flc];
            }
            gates_sh[fb0][flc] = g0;
            gates_sh[fb1][flc] = g1;
        }
        __syncthreads();

        // ---- elementwise LSTM update + h broadcast ----
        if (tid < 128) {
            float iv = gates_sh[ub][uu];
            float fv = gates_sh[ub][32 + uu];
            float gv = gates_sh[ub][64 + uu];
            float ov = gates_sh[ub][96 + uu];
            float ig = 1.f / (1.f + expf(-iv));
            float fg = 1.f / (1.f + expf(-fv));
            float gg = tanhf(gv);
            float og = 1.f / (1.f + expf(-ov));
            float c_old = c_sh[ub][uu];
            float c_new = fg * c_old + ig * gg;
            float h_new = og * tanhf(c_new);
            bool  m     = (msk[ub][t] != 0);
            float c_keep = m ? c_new : c_old;
            float h_old  = h_sh[cur][ub][32 * r + uu];
            float h_keep = m ? h_new : h_old;
            c_sh[ub][uu] = c_keep;
            g_states[((size_t)(bb0 + ub) * T_ + t) * H_ + 32 * r + uu] = m ? h_new : 0.f;
            // push carried h to all 8 ranks' next buffer (incl. self)
            uint32_t a = haddr[nxt];
#pragma unroll
            for (int p = 0; p < CLS_; ++p) st_cluster_f32(a, (uint32_t)p, h_keep);
        }
        cluster_sync_();  // orders DSMEM h pushes before next step's reads
    }
}

// ===========================================================================
// Kernel C: per-(b,t) NLL partials (deterministic fixed-order reduction)
// query[a] = sum_k emb[qit][k]*state[k]*Wq[a][k] + bq[a];  2-way log-softmax
// ===========================================================================
__global__ void nll_kernel(const int* __restrict__ items,
                           const int* __restrict__ actions,
                           const float* __restrict__ trans_emb,
                           const float* __restrict__ Wq,
                           const float* __restrict__ bq) {
    const int tid  = threadIdx.x;
    const int lane = tid & 31;
    const int wid  = tid >> 5;
    const int gw   = blockIdx.x * 8 + wid;   // 1024 warps total

    double wsum = 0.0;
    int    wcnt = 0;

    for (int p = gw; p < B_ * T_; p += 128 * 8) {
        int b = p / T_, t = p - b * T_;
        int qit = items[b * S_ + t + 1];
        if (qit != 0) {
            const float* er = &trans_emb[(size_t)qit * H_];
            const float* sr = &g_states[(size_t)p * H_];
            float d0 = 0.f, d1 = 0.f;
#pragma unroll
            for (int i = 0; i < 8; ++i) {
                int k = lane + 32 * i;
                float e = er[k] * sr[k];
                d0 += e * Wq[k];
                d1 += e * Wq[H_ + k];
            }
#pragma unroll
            for (int o = 16; o > 0; o >>= 1) {
                d0 += __shfl_xor_sync(0xffffffffu, d0, o);
                d1 += __shfl_xor_sync(0xffffffffu, d1, o);
            }
            float q0 = d0 + bq[0];
            float q1 = d1 + bq[1];
            float mx = fmaxf(q0, q1);
            float lse = mx + logf(expf(q0 - mx) + expf(q1 - mx));
            int tgt = actions[b * S_ + t + 1];
            float nll = lse - (tgt ? q1 : q0);
            if (lane == 0) { wsum += (double)nll; wcnt += 1; }
        }
    }

    __shared__ double ssum[8];
    __shared__ int    scnt[8];
    if (lane == 0) { ssum[wid] = wsum; scnt[wid] = wcnt; }
    __syncthreads();
    if (tid == 0) {
        double s = 0.0; int c = 0;
        for (int w = 0; w < 8; ++w) { s += ssum[w]; c += scnt[w]; }
        g_psum[blockIdx.x] = s;
        g_pcnt[blockIdx.x] = c;
    }
}

// Kernel D: final serial reduction -> loss
__global__ void finish_kernel(float* __restrict__ out) {
    if (threadIdx.x == 0) {
        double s = 0.0; long long c = 0;
        for (int i = 0; i < 128; ++i) { s += g_psum[i]; c += g_pcnt[i]; }
        out[0] = (float)(s / (double)c);
    }
}

// ===========================================================================
extern "C" void kernel_launch(void* const* d_in, const int* in_sizes, int n_in,
                              void* d_out, int out_size) {
    const int*   items     = (const int*)d_in[0];
    const int*   actions   = (const int*)d_in[1];
    const float* WihT      = (const float*)d_in[2];
    const float* Whh       = (const float*)d_in[3];
    const float* b_lstm    = (const float*)d_in[4];
    const float* trans_emb = (const float*)d_in[5];
    const float* Wq        = (const float*)d_in[6];
    const float* bq        = (const float*)d_in[7];

    // A: precompute masked x_proj + bias  (B*T*1024 floats / 4 / 256 = 12736 blocks)
    xpre_kernel<<<(B_ * T_ * 1024 / 4) / 256, 256>>>(items, actions, WihT, b_lstm);
    // B: clustered recurrence (16 clusters x 8 CTAs)
    lstm_kernel<<<128, 256>>>(items, Whh);
    // C: NLL partials
    nll_kernel<<<128, 256>>>(items, actions, trans_emb, Wq, bq);
    // D: final loss
    finish_kernel<<<1, 32>>>((float*)d_out);
}

// round 11
// speedup vs baseline: 1.0468x; 1.0468x over previous
#include <cuda_runtime.h>
#include <cstdint>
#include <cstddef>

// Problem constants
#define NI_   50000
#define B_    64
#define S_    200
#define T_    199      // S-1 recurrent steps
#define H_    256
#define CLS_  8        // CTAs per cluster
#define NB_   4        // batches per cluster
#define THR_  512

// -------- device-global scratch --------
__device__ float  g_states[(size_t)B_ * T_ * H_];   // masked h outputs, 13 MB
__device__ double g_psum[128];
__device__ int    g_pcnt[128];
__device__ int    g_done = 0;

// -------- packed f32x2 helpers --------
static __device__ __forceinline__ unsigned long long ffma2(unsigned long long a,
                                                           unsigned long long b,
                                                           unsigned long long c) {
    unsigned long long d;
    asm("fma.rn.f32x2 %0, %1, %2, %3;" : "=l"(d) : "l"(a), "l"(b), "l"(c));
    return d;
}
static __device__ __forceinline__ unsigned long long pack2(float x, float y) {
    unsigned long long u;
    asm("mov.b64 %0, {%1, %2};" : "=l"(u) : "f"(x), "f"(y));
    return u;
}
static __device__ __forceinline__ float2 unpack2(unsigned long long u) {
    float2 r;
    asm("mov.b64 {%0, %1}, %2;" : "=f"(r.x), "=f"(r.y) : "l"(u));
    return r;
}
static __device__ __forceinline__ uint32_t smem_u32(const void* p) {
    uint32_t a;
    asm("{ .reg .u64 t; cvta.to.shared.u64 t, %1; cvt.u32.u64 %0, t; }" : "=r"(a) : "l"(p));
    return a;
}
static __device__ __forceinline__ uint32_t ctarank_() {
    uint32_t r; asm("mov.u32 %0, %%cluster_ctarank;" : "=r"(r)); return r;
}
static __device__ __forceinline__ void cluster_sync_() {
    asm volatile("barrier.cluster.arrive.aligned;" ::: "memory");
    asm volatile("barrier.cluster.wait.aligned;" ::: "memory");
}
static __device__ __forceinline__ void mbar_init_(uint32_t a, uint32_t cnt) {
    asm volatile("mbarrier.init.shared.b64 [%0], %1;" :: "r"(a), "r"(cnt) : "memory");
}
static __device__ __forceinline__ void mbar_expect_tx_(uint32_t a, uint32_t bytes) {
    asm volatile("mbarrier.arrive.expect_tx.shared.b64 _, [%0], %1;"
                 :: "r"(a), "r"(bytes) : "memory");
}
static __device__ __forceinline__ void mbar_wait_(uint32_t a, uint32_t parity) {
    asm volatile(
        "{\n\t.reg .pred P;\n\t"
        "LW%=:\n\t"
        "mbarrier.try_wait.parity.acquire.cta.shared::cta.b64 P, [%0], %1, 0x989680;\n\t"
        "@P bra LD%=;\n\t"
        "bra LW%=;\n\t"
        "LD%=:\n\t}"
        :: "r"(a), "r"(parity) : "memory");
}
static __device__ __forceinline__ uint32_t mapa_(uint32_t a, uint32_t rank) {
    uint32_t d;
    asm("mapa.shared::cluster.u32 %0, %1, %2;" : "=r"(d) : "r"(a), "r"(rank));
    return d;
}
static __device__ __forceinline__ void bulk_dsmem_(uint32_t dst_cluster, uint32_t src_cta,
                                                   uint32_t bytes, uint32_t mbar_cluster) {
    asm volatile(
        "cp.async.bulk.shared::cluster.shared::cta.mbarrier::complete_tx::bytes "
        "[%0], [%1], %2, [%3];"
        :: "r"(dst_cluster), "r"(src_cta), "r"(bytes), "r"(mbar_cluster) : "memory");
}

// ===========================================================================
// Kernel 1: clustered LSTM recurrence. 16 clusters x 8 CTAs, 512 thr/CTA.
// Cluster owns batches [4c,4c+4). Rank r owns hidden units [32r,32r+32)
// = 128 local gate columns. Thread: kg=tid>>6 (K chunk of 32), 2 gate cols.
// Weights register-resident as f32x2 (32 regs/thread). Per step: FMA ->
// split-K partials in SMEM -> 1 syncthreads -> 128 update threads do
// activations + mask + stage h-slice -> 8 cp.async.bulk DSMEM pushes with
// complete_tx on peers' phase mbarrier. x_proj gathered from WihT inline,
// prefetched one step ahead.
// ===========================================================================
__global__ __launch_bounds__(THR_, 1) __cluster_dims__(CLS_, 1, 1)
void lstm_kernel(const int* __restrict__ items, const int* __restrict__ actions,
                 const float* __restrict__ Whh, const float* __restrict__ WihT,
                 const float* __restrict__ b_lstm) {
    __shared__ __align__(16) float h_sh[2][CLS_][NB_][32];  // 8 KB (rank-major)
    __shared__ __align__(16) float part[8][NB_][128];       // 16 KB
    __shared__ __align__(16) float x_sh[2][NB_][128];       // 4 KB
    __shared__ __align__(16) float hstage[NB_][32];         // 512 B
    __shared__ float c_sh[NB_][32];
    __shared__ int   it_s[NB_][S_];
    __shared__ int   ac_s[NB_][S_];
    __shared__ __align__(8) unsigned long long mbar_arr[2];

    const int tid = threadIdx.x;
    const int r   = (int)ctarank_();
    const int bb0 = (blockIdx.x / CLS_) * NB_;

    // FMA mapping: 8 K-groups x 64 threads x 2 cols
    const int kg = tid >> 6;
    const int c0 = 2 * (tid & 63);       // local cols c0, c0+1

    // ---- weight slice -> registers (2 cols x 32 K = 32 f32x2) ----
    unsigned long long w2r[2][16];
#pragma unroll
    for (int c = 0; c < 2; ++c) {
        int lc = c0 + c;
        int gc = (lc >> 5) * 256 + 32 * r + (lc & 31);
        const float2* wrow = (const float2*)&Whh[(size_t)gc * H_ + 32 * kg];
#pragma unroll
        for (int kk = 0; kk < 16; ++kk) {
            float2 wv = wrow[kk];
            w2r[c][kk] = pack2(wv.x, wv.y);
        }
    }

    // x mapping: thread -> (bx, colx)
    const int bx   = tid >> 7;           // 0..3
    const int colx = tid & 127;
    const int gcx  = (colx >> 5) * 256 + 32 * r + (colx & 31);
    const float bias = b_lstm[gcx];

    // ---- init smem ----
    for (int i = tid; i < 2 * CLS_ * NB_ * 32; i += THR_) ((float*)h_sh)[i] = 0.f;
    for (int i = tid; i < NB_ * 32; i += THR_) ((float*)c_sh)[i] = 0.f;
    for (int i = tid; i < NB_ * S_; i += THR_) {
        int b = i / S_, s = i - b * S_;
        it_s[b][s] = items[(bb0 + b) * S_ + s];
        ac_s[b][s] = actions[(bb0 + b) * S_ + s];
    }
    const uint32_t mb0 = smem_u32(&mbar_arr[0]);
    const uint32_t mb1 = smem_u32(&mbar_arr[1]);
    if (tid == 0) {
        mbar_init_(mb0, 1); mbar_init_(mb1, 1);
        mbar_expect_tx_(mb0, 4096);      // pre-arm for h(2)
        mbar_expect_tx_(mb1, 4096);      // pre-arm for h(1)
    }
    __syncthreads();
    cluster_sync_();   // all barriers live before any push

    const uint32_t hst_src  = smem_u32(&hstage[0][0]);
    const uint32_t hdst0    = smem_u32(&h_sh[0][r][0][0]);
    const uint32_t hdst1    = smem_u32(&h_sh[1][r][0][0]);

    // prefetch x inputs for t=0
    int   nm  = (it_s[bx][0] != 0);
    float nw1 = WihT[(size_t)it_s[bx][0] * 1024 + gcx];
    float nw2 = WihT[(size_t)(NI_ + ac_s[bx][0]) * 1024 + gcx];

    int ph0 = 0, ph1 = 0;

    for (int t = 0; t < T_; ++t) {
        const int cur = t & 1;
        const int nxt = cur ^ 1;

        // finalize x(t); prefetch x(t+1) (latency hidden by FMA loop)
        float xv = (nm ? (nw1 + nw2) : 0.f) + bias;
        if (t + 1 < T_) {
            int it = it_s[bx][t + 1], ac = ac_s[bx][t + 1];
            nm  = (it != 0);
            nw1 = WihT[(size_t)it * 1024 + gcx];
            nw2 = WihT[(size_t)(NI_ + ac) * 1024 + gcx];
        }

        // wait for h(t) (t=0: buffers pre-zeroed); re-arm barrier for t+2
        if (t > 0) {
            if (cur) { mbar_wait_(mb1, ph1); ph1 ^= 1; }
            else     { mbar_wait_(mb0, ph0); ph0 ^= 1; }
            if (tid == 0) mbar_expect_tx_(cur ? mb1 : mb0, 4096);
        }

        // ---- FMA: 2 cols x 4 batches x 32 K = 128 FFMA2/thread ----
        unsigned long long acc[2][4];
#pragma unroll
        for (int c = 0; c < 2; ++c)
#pragma unroll
            for (int b = 0; b < 4; ++b) acc[c][b] = 0ull;

#pragma unroll
        for (int k4 = 0; k4 < 8; ++k4) {
            ulonglong2 hv[4];
#pragma unroll
            for (int b = 0; b < 4; ++b)
                hv[b] = *(const ulonglong2*)&h_sh[cur][kg][b][4 * k4];
#pragma unroll
            for (int b = 0; b < 4; ++b) {
#pragma unroll
                for (int c = 0; c < 2; ++c) {
                    acc[c][b] = ffma2(w2r[c][2 * k4],     hv[b].x, acc[c][b]);
                    acc[c][b] = ffma2(w2r[c][2 * k4 + 1], hv[b].y, acc[c][b]);
                }
            }
        }

        x_sh[cur][bx][colx] = xv;
#pragma unroll
        for (int b = 0; b < 4; ++b) {
            float2 f0 = unpack2(acc[0][b]);
            float2 f1 = unpack2(acc[1][b]);
            float2 v; v.x = f0.x + f0.y; v.y = f1.x + f1.y;
            *(float2*)&part[kg][b][c0] = v;
        }
        __syncthreads();

        // ---- update (128 threads, one per (b,u)) ----
        if (tid < 128) {
            const int b = tid >> 5, u = tid & 31;
            float g0 = x_sh[cur][b][u];
            float g1 = x_sh[cur][b][32 + u];
            float g2 = x_sh[cur][b][64 + u];
            float g3 = x_sh[cur][b][96 + u];
#pragma unroll
            for (int k = 0; k < 8; ++k) {
                g0 += part[k][b][u];
                g1 += part[k][b][32 + u];
                g2 += part[k][b][64 + u];
                g3 += part[k][b][96 + u];
            }
            float ig = 1.f / (1.f + expf(-g0));
            float fg = 1.f / (1.f + expf(-g1));
            float gg = tanhf(g2);
            float og = 1.f / (1.f + expf(-g3));
            float c_old = c_sh[b][u];
            float c_new = fg * c_old + ig * gg;
            float h_new = og * tanhf(c_new);
            bool  m = (it_s[b][t] != 0);
            float h_old = h_sh[cur][r][b][u];
            c_sh[b][u]   = m ? c_new : c_old;
            hstage[b][u] = m ? h_new : h_old;
            g_states[((size_t)(bb0 + b) * T_ + t) * H_ + 32 * r + u] = m ? h_new : 0.f;
            asm volatile("bar.sync 1, 128;" ::: "memory");
            if (tid == 0 && t + 1 < T_) {
                asm volatile("fence.proxy.async.shared::cta;" ::: "memory");
                uint32_t dl = (nxt ? hdst1 : hdst0);
                uint32_t ml = (nxt ? mb1 : mb0);
#pragma unroll
                for (int p = 0; p < CLS_; ++p)
                    bulk_dsmem_(mapa_(dl, (uint32_t)p), hst_src, 512,
                                mapa_(ml, (uint32_t)p));
            }
        }
        // no trailing barrier: next step's SMEM writes are gated by the
        // mbarrier wait, whose tx includes our own push (issued only after
        // all 128 update threads drained part/x_sh/h_old).
    }
    cluster_sync_();   // keep smem alive until in-flight DSMEM ops settle
}

// ===========================================================================
// Kernel 2: NLL partials + deterministic last-block finish.
// ===========================================================================
__global__ void nll_kernel(const int* __restrict__ items,
                           const int* __restrict__ actions,
                           const float* __restrict__ trans_emb,
                           const float* __restrict__ Wq,
                           const float* __restrict__ bq,
                           float* __restrict__ out) {
    const int tid  = threadIdx.x;
    const int lane = tid & 31;
    const int wid  = tid >> 5;
    const int gw   = blockIdx.x * 8 + wid;

    double wsum = 0.0;
    int    wcnt = 0;

    for (int p = gw; p < B_ * T_; p += 128 * 8) {
        int b = p / T_, t = p - b * T_;
        int qit = items[b * S_ + t + 1];
        if (qit != 0) {
            const float* er = &trans_emb[(size_t)qit * H_];
            const float* sr = &g_states[(size_t)p * H_];
            float d0 = 0.f, d1 = 0.f;
#pragma unroll
            for (int i = 0; i < 8; ++i) {
                int k = lane + 32 * i;
                float e = er[k] * sr[k];
                d0 += e * Wq[k];
                d1 += e * Wq[H_ + k];
            }
#pragma unroll
            for (int o = 16; o > 0; o >>= 1) {
                d0 += __shfl_xor_sync(0xffffffffu, d0, o);
                d1 += __shfl_xor_sync(0xffffffffu, d1, o);
            }
            float q0 = d0 + bq[0];
            float q1 = d1 + bq[1];
            float mx = fmaxf(q0, q1);
            float lse = mx + logf(expf(q0 - mx) + expf(q1 - mx));
            int tgt = actions[b * S_ + t + 1];
            float nll = lse - (tgt ? q1 : q0);
            if (lane == 0) { wsum += (double)nll; wcnt += 1; }
        }
    }

    __shared__ double ssum[8];
    __shared__ int    scnt[8];
    if (lane == 0) { ssum[wid] = wsum; scnt[wid] = wcnt; }
    __syncthreads();
    if (tid == 0) {
        double s = 0.0; int c = 0;
        for (int w = 0; w < 8; ++w) { s += ssum[w]; c += scnt[w]; }
        g_psum[blockIdx.x] = s;
        g_pcnt[blockIdx.x] = c;
        __threadfence();
        if (atomicAdd(&g_done, 1) == 127) {
            double S = 0.0; long long C = 0;
            for (int i = 0; i < 128; ++i) { S += g_psum[i]; C += g_pcnt[i]; }
            out[0] = (float)(S / (double)C);
            __threadfence();
            g_done = 0;
        }
    }
}

// ===========================================================================
extern "C" void kernel_launch(void* const* d_in, const int* in_sizes, int n_in,
                              void* d_out, int out_size) {
    const int*   items     = (const int*)d_in[0];
    const int*   actions   = (const int*)d_in[1];
    const float* WihT      = (const float*)d_in[2];
    const float* Whh       = (const float*)d_in[3];
    const float* b_lstm    = (const float*)d_in[4];
    const float* trans_emb = (const float*)d_in[5];
    const float* Wq        = (const float*)d_in[6];
    const float* bq        = (const float*)d_in[7];

    lstm_kernel<<<128, THR_>>>(items, actions, Whh, WihT, b_lstm);
    nll_kernel<<<128, 256>>>(items, actions, trans_emb, Wq, bq, (float*)d_out);
}

// round 12
// speedup vs baseline: 1.0884x; 1.0397x over previous
#include <cuda_runtime.h>
#include <cstdint>
#include <cstddef>

// Problem constants
#define NI_   50000
#define B_    64
#define S_    200
#define T_    199      // S-1 recurrent steps
#define H_    256
#define CLS_  8        // CTAs per cluster
#define NB_   4        // batches per cluster
#define THR_  512
#define NLLB_ 148      // nll grid

// -------- device-global scratch --------
__device__ float  g_states[(size_t)B_ * T_ * H_];   // masked h outputs, 13 MB
__device__ double g_psum[NLLB_];
__device__ int    g_pcnt[NLLB_];
__device__ int    g_done = 0;

// -------- packed f32x2 helpers --------
static __device__ __forceinline__ unsigned long long ffma2(unsigned long long a,
                                                           unsigned long long b,
                                                           unsigned long long c) {
    unsigned long long d;
    asm("fma.rn.f32x2 %0, %1, %2, %3;" : "=l"(d) : "l"(a), "l"(b), "l"(c));
    return d;
}
static __device__ __forceinline__ unsigned long long pack2(float x, float y) {
    unsigned long long u;
    asm("mov.b64 %0, {%1, %2};" : "=l"(u) : "f"(x), "f"(y));
    return u;
}
static __device__ __forceinline__ float2 unpack2(unsigned long long u) {
    float2 r;
    asm("mov.b64 {%0, %1}, %2;" : "=f"(r.x), "=f"(r.y) : "l"(u));
    return r;
}
static __device__ __forceinline__ uint32_t smem_u32(const void* p) {
    uint32_t a;
    asm("{ .reg .u64 t; cvta.to.shared.u64 t, %1; cvt.u32.u64 %0, t; }" : "=r"(a) : "l"(p));
    return a;
}
static __device__ __forceinline__ uint32_t ctarank_() {
    uint32_t r; asm("mov.u32 %0, %%cluster_ctarank;" : "=r"(r)); return r;
}
static __device__ __forceinline__ void cluster_sync_() {
    asm volatile("barrier.cluster.arrive.aligned;" ::: "memory");
    asm volatile("barrier.cluster.wait.aligned;" ::: "memory");
}
static __device__ __forceinline__ void mbar_init_(uint32_t a, uint32_t cnt) {
    asm volatile("mbarrier.init.shared.b64 [%0], %1;" :: "r"(a), "r"(cnt) : "memory");
}
static __device__ __forceinline__ void mbar_expect_tx_(uint32_t a, uint32_t bytes) {
    asm volatile("mbarrier.arrive.expect_tx.shared.b64 _, [%0], %1;"
                 :: "r"(a), "r"(bytes) : "memory");
}
static __device__ __forceinline__ void mbar_wait_(uint32_t a, uint32_t parity) {
    asm volatile(
        "{\n\t.reg .pred P;\n\t"
        "LW%=:\n\t"
        "mbarrier.try_wait.parity.acquire.cta.shared::cta.b64 P, [%0], %1, 0x989680;\n\t"
        "@P bra LD%=;\n\t"
        "bra LW%=;\n\t"
        "LD%=:\n\t}"
        :: "r"(a), "r"(parity) : "memory");
}
static __device__ __forceinline__ uint32_t mapa_(uint32_t a, uint32_t rank) {
    uint32_t d;
    asm("mapa.shared::cluster.u32 %0, %1, %2;" : "=r"(d) : "r"(a), "r"(rank));
    return d;
}
static __device__ __forceinline__ void bulk_dsmem_(uint32_t dst_cluster, uint32_t src_cta,
                                                   uint32_t bytes, uint32_t mbar_cluster) {
    asm volatile(
        "cp.async.bulk.shared::cluster.shared::cta.mbarrier::complete_tx::bytes "
        "[%0], [%1], %2, [%3];"
        :: "r"(dst_cluster), "r"(src_cta), "r"(bytes), "r"(mbar_cluster) : "memory");
}

// ===========================================================================
// Kernel 1: clustered LSTM recurrence. 16 clusters x 8 CTAs, 512 thr/CTA.
// Cluster owns batches [4c,4c+4). Rank r owns hidden units [32r,32r+32)
// = 128 local gate columns. Thread: kg=tid>>6 (K chunk of 32), 2 gate cols.
// Weights register-resident as 32 f32x2 (64 regs). Inner loop keeps only ONE
// h-vector (ulonglong2) live at a time -> peak regs ~100, no spills.
// ===========================================================================
__global__ __launch_bounds__(THR_, 1) __cluster_dims__(CLS_, 1, 1)
void lstm_kernel(const int* __restrict__ items, const int* __restrict__ actions,
                 const float* __restrict__ Whh, const float* __restrict__ WihT,
                 const float* __restrict__ b_lstm) {
    __shared__ __align__(16) float h_sh[2][CLS_][NB_][32];  // 8 KB (rank-major)
    __shared__ __align__(16) float part[8][NB_][128];       // 16 KB
    __shared__ __align__(16) float x_sh[2][NB_][128];       // 4 KB
    __shared__ __align__(16) float hstage[NB_][32];         // 512 B
    __shared__ float c_sh[NB_][32];
    __shared__ int   it_s[NB_][S_];
    __shared__ int   ac_s[NB_][S_];
    __shared__ __align__(8) unsigned long long mbar_arr[2];

    const int tid = threadIdx.x;
    const int r   = (int)ctarank_();
    const int bb0 = (blockIdx.x / CLS_) * NB_;

    // FMA mapping: 8 K-groups x 64 threads x 2 cols
    const int kg = tid >> 6;
    const int c0 = 2 * (tid & 63);       // local cols c0, c0+1

    // ---- weight slice -> registers (2 cols x 32 K = 32 f32x2) ----
    unsigned long long w2r[2][16];
#pragma unroll
    for (int c = 0; c < 2; ++c) {
        int lc = c0 + c;
        int gc = (lc >> 5) * 256 + 32 * r + (lc & 31);
        const float2* wrow = (const float2*)&Whh[(size_t)gc * H_ + 32 * kg];
#pragma unroll
        for (int kk = 0; kk < 16; ++kk) {
            float2 wv = wrow[kk];
            w2r[c][kk] = pack2(wv.x, wv.y);
        }
    }

    // x mapping: thread -> (bx, colx)
    const int bx   = tid >> 7;           // 0..3
    const int colx = tid & 127;
    const int gcx  = (colx >> 5) * 256 + 32 * r + (colx & 31);
    const float bias = b_lstm[gcx];

    // ---- init smem ----
    for (int i = tid; i < 2 * CLS_ * NB_ * 32; i += THR_) ((float*)h_sh)[i] = 0.f;
    for (int i = tid; i < NB_ * 32; i += THR_) ((float*)c_sh)[i] = 0.f;
    for (int i = tid; i < NB_ * S_; i += THR_) {
        int b = i / S_, s = i - b * S_;
        it_s[b][s] = items[(bb0 + b) * S_ + s];
        ac_s[b][s] = actions[(bb0 + b) * S_ + s];
    }
    const uint32_t mb0 = smem_u32(&mbar_arr[0]);
    const uint32_t mb1 = smem_u32(&mbar_arr[1]);
    if (tid == 0) {
        mbar_init_(mb0, 1); mbar_init_(mb1, 1);
        mbar_expect_tx_(mb0, 4096);      // pre-arm for h(2)
        mbar_expect_tx_(mb1, 4096);      // pre-arm for h(1)
    }
    __syncthreads();
    cluster_sync_();   // all barriers live before any push

    const uint32_t hst_src  = smem_u32(&hstage[0][0]);
    const uint32_t hdst0    = smem_u32(&h_sh[0][r][0][0]);
    const uint32_t hdst1    = smem_u32(&h_sh[1][r][0][0]);

    // prefetch x inputs for t=0
    int   nm  = (it_s[bx][0] != 0);
    float nw1 = WihT[(size_t)it_s[bx][0] * 1024 + gcx];
    float nw2 = WihT[(size_t)(NI_ + ac_s[bx][0]) * 1024 + gcx];

    int ph0 = 0, ph1 = 0;

    for (int t = 0; t < T_; ++t) {
        const int cur = t & 1;
        const int nxt = cur ^ 1;

        // finalize x(t); prefetch x(t+1) (latency hidden by FMA loop)
        float xv = (nm ? (nw1 + nw2) : 0.f) + bias;
        if (t + 1 < T_) {
            int it = it_s[bx][t + 1], ac = ac_s[bx][t + 1];
            nm  = (it != 0);
            nw1 = WihT[(size_t)it * 1024 + gcx];
            nw2 = WihT[(size_t)(NI_ + ac) * 1024 + gcx];
        }

        // wait for h(t) (t=0: buffers pre-zeroed); re-arm barrier for t+2
        if (t > 0) {
            if (cur) { mbar_wait_(mb1, ph1); ph1 ^= 1; }
            else     { mbar_wait_(mb0, ph0); ph0 ^= 1; }
            if (tid == 0) mbar_expect_tx_(cur ? mb1 : mb0, 4096);
        }

        // ---- FMA: 2 cols x 4 batches x 32 K = 128 FFMA2/thread ----
        // Only ONE hv (2 regs) live at a time -> no spills.
        unsigned long long acc0[4], acc1[4];
#pragma unroll
        for (int b = 0; b < 4; ++b) { acc0[b] = 0ull; acc1[b] = 0ull; }

#pragma unroll
        for (int k4 = 0; k4 < 8; ++k4) {
#pragma unroll
            for (int b = 0; b < 4; ++b) {
                ulonglong2 hv = *(const ulonglong2*)&h_sh[cur][kg][b][4 * k4];
                acc0[b] = ffma2(w2r[0][2 * k4],     hv.x, acc0[b]);
                acc0[b] = ffma2(w2r[0][2 * k4 + 1], hv.y, acc0[b]);
                acc1[b] = ffma2(w2r[1][2 * k4],     hv.x, acc1[b]);
                acc1[b] = ffma2(w2r[1][2 * k4 + 1], hv.y, acc1[b]);
            }
        }

        x_sh[cur][bx][colx] = xv;
#pragma unroll
        for (int b = 0; b < 4; ++b) {
            float2 f0 = unpack2(acc0[b]);
            float2 f1 = unpack2(acc1[b]);
            float2 v; v.x = f0.x + f0.y; v.y = f1.x + f1.y;
            *(float2*)&part[kg][b][c0] = v;
        }
        __syncthreads();

        // ---- update (128 threads, one per (b,u)) ----
        if (tid < 128) {
            const int b = tid >> 5, u = tid & 31;
            float g0 = x_sh[cur][b][u];
            float g1 = x_sh[cur][b][32 + u];
            float g2 = x_sh[cur][b][64 + u];
            float g3 = x_sh[cur][b][96 + u];
#pragma unroll
            for (int k = 0; k < 8; ++k) {
                g0 += part[k][b][u];
                g1 += part[k][b][32 + u];
                g2 += part[k][b][64 + u];
                g3 += part[k][b][96 + u];
            }
            float ig = 1.f / (1.f + expf(-g0));
            float fg = 1.f / (1.f + expf(-g1));
            float gg = tanhf(g2);
            float og = 1.f / (1.f + expf(-g3));
            float c_old = c_sh[b][u];
            float c_new = fg * c_old + ig * gg;
            float h_new = og * tanhf(c_new);
            bool  m = (it_s[b][t] != 0);
            float h_old = h_sh[cur][r][b][u];
            c_sh[b][u]   = m ? c_new : c_old;
            hstage[b][u] = m ? h_new : h_old;
            g_states[((size_t)(bb0 + b) * T_ + t) * H_ + 32 * r + u] = m ? h_new : 0.f;
            asm volatile("bar.sync 1, 128;" ::: "memory");
            if (tid == 0 && t + 1 < T_) {
                asm volatile("fence.proxy.async.shared::cta;" ::: "memory");
                uint32_t dl = (nxt ? hdst1 : hdst0);
                uint32_t ml = (nxt ? mb1 : mb0);
#pragma unroll
                for (int p = 0; p < CLS_; ++p)
                    bulk_dsmem_(mapa_(dl, (uint32_t)p), hst_src, 512,
                                mapa_(ml, (uint32_t)p));
            }
        }
        // no trailing barrier: next step's SMEM writes are gated by the
        // mbarrier wait, whose tx includes our own push (issued only after
        // all 128 update threads drained part/x_sh/h_old).
    }
    cluster_sync_();   // keep smem alive until in-flight DSMEM ops settle
}

// ===========================================================================
// Kernel 2: NLL partials + deterministic last-block finish.
// 148 blocks x 512 threads (2.2x the parallelism of R11 -> latency-bound fix)
// ===========================================================================
__global__ __launch_bounds__(512) void nll_kernel(
        const int* __restrict__ items, const int* __restrict__ actions,
        const float* __restrict__ trans_emb, const float* __restrict__ Wq,
        const float* __restrict__ bq, float* __restrict__ out) {
    const int tid  = threadIdx.x;
    const int lane = tid & 31;
    const int wid  = tid >> 5;                 // 0..15
    const int gw   = blockIdx.x * 16 + wid;    // 2368 warps total

    double wsum = 0.0;
    int    wcnt = 0;

    for (int p = gw; p < B_ * T_; p += NLLB_ * 16) {
        int b = p / T_, t = p - b * T_;
        int qit = items[b * S_ + t + 1];
        if (qit != 0) {
            const float* er = &trans_emb[(size_t)qit * H_];
            const float* sr = &g_states[(size_t)p * H_];
            float d0 = 0.f, d1 = 0.f;
#pragma unroll
            for (int i = 0; i < 8; ++i) {
                int k = lane + 32 * i;
                float e = er[k] * sr[k];
                d0 += e * Wq[k];
                d1 += e * Wq[H_ + k];
            }
#pragma unroll
            for (int o = 16; o > 0; o >>= 1) {
                d0 += __shfl_xor_sync(0xffffffffu, d0, o);
                d1 += __shfl_xor_sync(0xffffffffu, d1, o);
            }
            float q0 = d0 + bq[0];
            float q1 = d1 + bq[1];
            float mx = fmaxf(q0, q1);
            float lse = mx + logf(expf(q0 - mx) + expf(q1 - mx));
            int tgt = actions[b * S_ + t + 1];
            float nll = lse - (tgt ? q1 : q0);
            if (lane == 0) { wsum += (double)nll; wcnt += 1; }
        }
    }

    __shared__ double ssum[16];
    __shared__ int    scnt[16];
    if (lane == 0) { ssum[wid] = wsum; scnt[wid] = wcnt; }
    __syncthreads();
    if (tid == 0) {
        double s = 0.0; int c = 0;
        for (int w = 0; w < 16; ++w) { s += ssum[w]; c += scnt[w]; }
        g_psum[blockIdx.x] = s;
        g_pcnt[blockIdx.x] = c;
        __threadfence();
        if (atomicAdd(&g_done, 1) == NLLB_ - 1) {
            double S = 0.0; long long C = 0;
            for (int i = 0; i < NLLB_; ++i) { S += g_psum[i]; C += g_pcnt[i]; }
            out[0] = (float)(S / (double)C);
            __threadfence();
            g_done = 0;
        }
    }
}

// ===========================================================================
extern "C" void kernel_launch(void* const* d_in, const int* in_sizes, int n_in,
                              void* d_out, int out_size) {
    const int*   items     = (const int*)d_in[0];
    const int*   actions   = (const int*)d_in[1];
    const float* WihT      = (const float*)d_in[2];
    const float* Whh       = (const float*)d_in[3];
    const float* b_lstm    = (const float*)d_in[4];
    const float* trans_emb = (const float*)d_in[5];
    const float* Wq        = (const float*)d_in[6];
    const float* bq        = (const float*)d_in[7];

    lstm_kernel<<<128, THR_>>>(items, actions, Whh, WihT, b_lstm);
    nll_kernel<<<NLLB_, 512>>>(items, actions, trans_emb, Wq, bq, (float*)d_out);
}